// round 4
// baseline (speedup 1.0000x reference)
#include <cuda_runtime.h>
#include <cstdint>
#include <cstddef>

#define BATCH 64
#define SEQ   512
#define HID   300
#define UN    512
#define G3    1536
#define NCTA  128
#define NTH   512
#define NW    16
#define KW    32   // 512 / NW

// ---------------- scratch (device globals: allocation-free rule) ----------------
static __device__ float g_xg[(size_t)SEQ * G3 * BATCH];   // [s][k3][b]
static __device__ float g_y0[(size_t)SEQ * BATCH * UN];   // [s][b][u]
static __device__ float g_h[2][UN][BATCH];                // double-buffered h
static __device__ unsigned g_count;
static __device__ unsigned g_gen;

union F2U { unsigned long long u; float2 f; };

__device__ __forceinline__ unsigned long long ffma2(unsigned long long a,
                                                    unsigned long long b,
                                                    unsigned long long c) {
    unsigned long long d;
    asm("fma.rn.f32x2 %0, %1, %2, %3;" : "=l"(d) : "l"(a), "l"(b), "l"(c));
    return d;
}

__device__ __forceinline__ float sigf(float x) {
    return __fdividef(1.f, 1.f + __expf(-x));
}
__device__ __forceinline__ float tanhfast(float x) {
    float y; asm("tanh.approx.f32 %0, %1;" : "=f"(y) : "f"(x)); return y;
}

// acquire/release grid barrier (no membar.gpu / L1 flush). thread 0 of each CTA.
__device__ __forceinline__ void grid_bar(unsigned target, unsigned base) {
    unsigned old;
    asm volatile("atom.acq_rel.gpu.global.add.u32 %0, [%1], 1;"
                 : "=r"(old) : "l"(&g_count) : "memory");
    if (old == NCTA - 1u) {
        asm volatile("st.relaxed.gpu.global.u32 [%0], %1;" :: "l"(&g_count), "r"(0u) : "memory");
        asm volatile("red.release.gpu.global.add.u32 [%0], %1;" :: "l"(&g_gen), "r"(1u) : "memory");
    } else {
        unsigned g;
        do {
            asm volatile("ld.acquire.gpu.global.u32 %0, [%1];" : "=r"(g) : "l"(&g_gen) : "memory");
        } while ((unsigned)(g - base) < target);
    }
}

// ---------------- layer-0 input projection (FFMA2) ----------------
__global__ void __launch_bounds__(256) proj0_kernel(const int* __restrict__ tokens,
                                                    const float* __restrict__ emb,
                                                    const float* __restrict__ W0,
                                                    const float* __restrict__ b0) {
    __shared__ __align__(16) float2 Ws2[20][128];
    __shared__ __align__(16) float  Es[20][68];
    __shared__ int toks[BATCH];

    const int t  = threadIdx.x;
    const int s  = blockIdx.y;
    const int k0 = blockIdx.x * 128;
    if (t < BATCH) toks[t] = tokens[t * SEQ + s];
    __syncthreads();

    const int tk = t & 15, tb = t >> 4;
    unsigned long long acc[8][2];
#pragma unroll
    for (int i = 0; i < 8; ++i) { acc[i][0] = 0ull; acc[i][1] = 0ull; }

    for (int it = 0; it < 15; ++it) {
        const int d0 = it * 20;
        for (int idx = t; idx < 20 * 128; idx += 256) {
            int r = idx >> 7, c = idx & 127;
            float v = W0[(size_t)(d0 + r) * G3 + k0 + c];
            Ws2[r][c] = make_float2(v, v);
        }
        for (int idx = t; idx < 20 * BATCH; idx += 256) {
            int b = idx / 20, d = idx % 20;
            Es[d][b] = emb[(size_t)toks[b] * HID + d0 + d];
        }
        __syncthreads();
#pragma unroll
        for (int d = 0; d < 20; ++d) {
            ulonglong2 es = *(const ulonglong2*)&Es[d][tb * 4];
            const ulonglong2* wp = (const ulonglong2*)&Ws2[d][tk * 8];
#pragma unroll
            for (int ii = 0; ii < 4; ++ii) {
                ulonglong2 w2 = wp[ii];
                acc[2*ii  ][0] = ffma2(w2.x, es.x, acc[2*ii  ][0]);
                acc[2*ii  ][1] = ffma2(w2.x, es.y, acc[2*ii  ][1]);
                acc[2*ii+1][0] = ffma2(w2.y, es.x, acc[2*ii+1][0]);
                acc[2*ii+1][1] = ffma2(w2.y, es.y, acc[2*ii+1][1]);
            }
        }
        __syncthreads();
    }
#pragma unroll
    for (int i = 0; i < 8; ++i) {
        const int k = k0 + tk * 8 + i;
        const float bias = b0[k];
        F2U a0, a1; a0.u = acc[i][0]; a1.u = acc[i][1];
        float* dst = &g_xg[((size_t)s * G3 + k) * BATCH + tb * 4];
        dst[0] = a0.f.x + bias;
        dst[1] = a0.f.y + bias;
        dst[2] = a1.f.x + bias;
        dst[3] = a1.f.y + bias;
    }
}

// ---------------- layer-1 input projection (FFMA2) ----------------
__global__ void __launch_bounds__(256) proj1_kernel(const float* __restrict__ W1,
                                                    const float* __restrict__ b1) {
    __shared__ __align__(16) float2 Ws2[32][128];
    __shared__ __align__(16) float  Es[32][68];

    const int t  = threadIdx.x;
    const int s  = blockIdx.y;
    const int k0 = blockIdx.x * 128;
    const int tk = t & 15, tb = t >> 4;

    unsigned long long acc[8][2];
#pragma unroll
    for (int i = 0; i < 8; ++i) { acc[i][0] = 0ull; acc[i][1] = 0ull; }

    for (int it = 0; it < 16; ++it) {
        const int u0 = it * 32;
        for (int idx = t; idx < 32 * 128; idx += 256) {
            int r = idx >> 7, c = idx & 127;
            float v = W1[(size_t)(u0 + r) * G3 + k0 + c];
            Ws2[r][c] = make_float2(v, v);
        }
        for (int idx = t; idx < 32 * BATCH; idx += 256) {
            int b = idx >> 5, u = idx & 31;
            Es[u][b] = g_y0[((size_t)s * BATCH + b) * UN + u0 + u];
        }
        __syncthreads();
#pragma unroll
        for (int d = 0; d < 32; ++d) {
            ulonglong2 es = *(const ulonglong2*)&Es[d][tb * 4];
            const ulonglong2* wp = (const ulonglong2*)&Ws2[d][tk * 8];
#pragma unroll
            for (int ii = 0; ii < 4; ++ii) {
                ulonglong2 w2 = wp[ii];
                acc[2*ii  ][0] = ffma2(w2.x, es.x, acc[2*ii  ][0]);
                acc[2*ii  ][1] = ffma2(w2.x, es.y, acc[2*ii  ][1]);
                acc[2*ii+1][0] = ffma2(w2.y, es.x, acc[2*ii+1][0]);
                acc[2*ii+1][1] = ffma2(w2.y, es.y, acc[2*ii+1][1]);
            }
        }
        __syncthreads();
    }
#pragma unroll
    for (int i = 0; i < 8; ++i) {
        const int k = k0 + tk * 8 + i;
        const float bias = b1[k];
        F2U a0, a1; a0.u = acc[i][0]; a1.u = acc[i][1];
        float* dst = &g_xg[((size_t)s * G3 + k) * BATCH + tb * 4];
        dst[0] = a0.f.x + bias;
        dst[1] = a0.f.y + bias;
        dst[2] = a1.f.x + bias;
        dst[3] = a1.f.y + bias;
    }
}

// ---------------- persistent GRU scan ----------------
// 128 CTAs x 512 threads. CTA = 8 unit-cols x 32 batch. U slice duplicated as
// f32x2 pairs in SMEM. 16 warps split K (32 each); FFMA2 inner loop; SMEM
// partial reduce; register-resident hprev; acquire/release grid barrier.
__global__ void __launch_bounds__(NTH, 1) gru_scan(const float* __restrict__ Umat,
                                                   const float* __restrict__ brec,
                                                   int layer1, float* __restrict__ out) {
    extern __shared__ float sm[];
    float2* u2    = (float2*)sm;          // 512*24 float2 = 24576 floats (96KB)
    float* part   = sm + 24576;           // [16][768] = 12288 floats (48KB)
    float* rg_s   = part + 12288;         // [768]
    float* bias_s = rg_s + 768;           // [768]

    const int t  = threadIdx.x;
    const int l  = t & 31;
    const int w  = t >> 5;
    const int c0 = (blockIdx.x >> 1) * 8;
    const int b0 = (blockIdx.x & 1) * 32;

    __shared__ unsigned s_base;
    if (t == 0) {
        unsigned gcur;
        asm volatile("ld.relaxed.gpu.global.u32 %0, [%1];" : "=r"(gcur) : "l"(&g_gen) : "memory");
        s_base = gcur;
    }

    // U slice, duplicated: u2[k*24 + g*8 + c] = (U[k][g*512+c0+c], same)
    for (int idx = t; idx < 512 * 24; idx += NTH) {
        int k = idx / 24, j = idx % 24;
        int g = j >> 3, c = j & 7;
        float v = Umat[(size_t)k * G3 + g * UN + c0 + c];
        u2[idx] = make_float2(v, v);
    }
    // recurrent bias mapped to output layout o = (g*8+c)*32+b
    for (int idx = t; idx < 768; idx += NTH) {
        int g = idx >> 8, c = (idx >> 5) & 7;
        bias_s[idx] = brec[g * UN + c0 + c];
    }
    // zero h buffer 0
    for (int idx = blockIdx.x * NTH + t; idx < UN * BATCH; idx += NCTA * NTH)
        __stcg(&(&g_h[0][0][0])[idx], 0.f);
    __syncthreads();
    const unsigned base = s_base;
    if (t == 0) grid_bar(1, base);
    __syncthreads();

    unsigned nbar = 1;
    int p = 0;
    float hprev = 0.f;
    const int gb_c  = t & 7;    // gate-thread col (t < 256)
    const int gb_bb = t >> 3;   // gate-thread batch

    for (int s = 0; s < SEQ; ++s) {
        // prefetch xg for gate threads (consumed after the dot loop)
        float xz = 0.f, xr = 0.f, xh = 0.f;
        if (t < 256) {
            const size_t bx = (size_t)s * G3 * BATCH;
            const int gc = c0 + gb_c, gbb = b0 + gb_bb;
            xz = __ldg(&g_xg[bx + (size_t)gc * BATCH + gbb]);
            xr = __ldg(&g_xg[bx + (size_t)(UN + gc) * BATCH + gbb]);
            xh = __ldg(&g_xg[bx + (size_t)(2 * UN + gc) * BATCH + gbb]);
        }

        const int kbase = w * KW;
        const int bp = l & 15, ch = l >> 4;
        unsigned long long acc[12];
#pragma unroll
        for (int i = 0; i < 12; ++i) acc[i] = 0ull;

        const unsigned long long* hrow = (const unsigned long long*)
            ((const float*)g_h + ((size_t)p * UN + kbase) * BATCH + b0 + 2 * bp);
        const float2* ubase = u2 + (size_t)kbase * 24 + ch * 4;
#pragma unroll 8
        for (int kk = 0; kk < KW; ++kk) {
            unsigned long long h2 = __ldcg(hrow + (size_t)kk * (BATCH / 2));
            const ulonglong2* up = (const ulonglong2*)(ubase + (size_t)kk * 24);
#pragma unroll
            for (int g = 0; g < 3; ++g) {
                ulonglong2 ua = up[g * 4];
                ulonglong2 ub = up[g * 4 + 1];
                acc[g*4+0] = ffma2(h2, ua.x, acc[g*4+0]);
                acc[g*4+1] = ffma2(h2, ua.y, acc[g*4+1]);
                acc[g*4+2] = ffma2(h2, ub.x, acc[g*4+2]);
                acc[g*4+3] = ffma2(h2, ub.y, acc[g*4+3]);
            }
        }
        // partials: part[w][(g*8 + ch*4 + ci)*32 + 2bp(+1)]
        {
            float* pw = part + w * 768 + ch * 128 + 2 * bp;
#pragma unroll
            for (int g = 0; g < 3; ++g)
#pragma unroll
                for (int ci = 0; ci < 4; ++ci)
                    *(unsigned long long*)&pw[g * 256 + ci * 32] = acc[g * 4 + ci];
        }
        __syncthreads();

        // reduce 16 partials + bias -> rg_s[768]
        {
            float v = bias_s[t];
#pragma unroll
            for (int ww = 0; ww < NW; ++ww) v += part[ww * 768 + t];
            rg_s[t] = v;
            if (t < 256) {
                float v2 = bias_s[512 + t];
#pragma unroll
                for (int ww = 0; ww < NW; ++ww) v2 += part[ww * 768 + 512 + t];
                rg_s[512 + t] = v2;
            }
        }
        __syncthreads();

        if (t < 256) {
            const int c = gb_c, bb = gb_bb;
            const int o = c * 32 + bb;
            const float rz = rg_s[o], rr = rg_s[256 + o], rh = rg_s[512 + o];
            const float z  = sigf(xz + rz);
            const float r  = sigf(xr + rr);
            const float hh = tanhfast(xh + r * rh);
            const float hn = z * hprev + (1.f - z) * hh;
            hprev = hn;
            const int gc = c0 + c, gbb = b0 + bb;
            __stcg(&g_h[p ^ 1][gc][gbb], hn);
            if (!layer1) {
                g_y0[((size_t)s * BATCH + gbb) * UN + gc] = hn;
            } else {
                out[((size_t)gbb * SEQ + s) * UN + gc] = hn;
                if (s == SEQ - 1)
                    out[(size_t)BATCH * SEQ * UN + (size_t)gbb * UN + gc] = hn;
            }
        }
        p ^= 1;
        if (s != SEQ - 1) {
            __syncthreads();
            if (t == 0) grid_bar(++nbar, base);
            __syncthreads();
        }
    }
}

// ---------------- launch ----------------
extern "C" void kernel_launch(void* const* d_in, const int* in_sizes, int n_in,
                              void* d_out, int out_size) {
    const int*   tokens = (const int*)d_in[0];
    const float* emb    = (const float*)d_in[1];
    const float* W0     = (const float*)d_in[2];
    const float* U0     = (const float*)d_in[3];
    const float* b0     = (const float*)d_in[4];
    const float* W1     = (const float*)d_in[5];
    const float* U1     = (const float*)d_in[6];
    const float* b1     = (const float*)d_in[7];
    float* out = (float*)d_out;

    // u2 (24576 floats) + part (12288) + rg_s (768) + bias_s (768) = 38400 floats = 150 KB
    const size_t shmem = (24576 + 12288 + 768 + 768) * sizeof(float);
    cudaFuncSetAttribute(gru_scan, cudaFuncAttributeMaxDynamicSharedMemorySize, (int)shmem);

    dim3 pgrid(12, 512);
    proj0_kernel<<<pgrid, 256>>>(tokens, emb, W0, b0);
    gru_scan<<<NCTA, NTH, shmem>>>(U0, b0 + G3, 0, nullptr);
    proj1_kernel<<<pgrid, 256>>>(W1, b1);
    gru_scan<<<NCTA, NTH, shmem>>>(U1, b1 + G3, 1, out);
}

// round 5
// speedup vs baseline: 1.0000x; 1.0000x over previous
#include <cuda_runtime.h>
#include <cstdint>
#include <cstddef>

#define BATCH 64
#define SEQ   512
#define HID   300
#define UN    512
#define G3    1536
#define NCTA  128
#define NTH   512
#define NW    16
#define KW    32   // 512 / NW

// ---------------- scratch (device globals: allocation-free rule) ----------------
static __device__ float g_xg[(size_t)SEQ * G3 * BATCH];   // [s][k3][b]
static __device__ float g_y0[(size_t)SEQ * BATCH * UN];   // [s][b][u]
static __device__ float g_h[2][UN][BATCH];                // double-buffered h
static __device__ unsigned g_count;
static __device__ unsigned g_gen;

union F2U { unsigned long long u; float2 f; };

__device__ __forceinline__ unsigned long long ffma2(unsigned long long a,
                                                    unsigned long long b,
                                                    unsigned long long c) {
    unsigned long long d;
    asm("fma.rn.f32x2 %0, %1, %2, %3;" : "=l"(d) : "l"(a), "l"(b), "l"(c));
    return d;
}

__device__ __forceinline__ float sigf(float x) {
    return __fdividef(1.f, 1.f + __expf(-x));
}
__device__ __forceinline__ float tanhfast(float x) {
    float y; asm("tanh.approx.f32 %0, %1;" : "=f"(y) : "f"(x)); return y;
}

// acquire/release grid barrier (no membar.gpu / L1 flush). thread 0 of each CTA.
__device__ __forceinline__ void grid_bar(unsigned target, unsigned base) {
    unsigned old;
    asm volatile("atom.acq_rel.gpu.global.add.u32 %0, [%1], 1;"
                 : "=r"(old) : "l"(&g_count) : "memory");
    if (old == NCTA - 1u) {
        asm volatile("st.relaxed.gpu.global.u32 [%0], %1;" :: "l"(&g_count), "r"(0u) : "memory");
        asm volatile("red.release.gpu.global.add.u32 [%0], %1;" :: "l"(&g_gen), "r"(1u) : "memory");
    } else {
        unsigned g;
        do {
            asm volatile("ld.acquire.gpu.global.u32 %0, [%1];" : "=r"(g) : "l"(&g_gen) : "memory");
        } while ((unsigned)(g - base) < target);
    }
}

// ---------------- layer-0 input projection (FFMA2) ----------------
__global__ void __launch_bounds__(256) proj0_kernel(const int* __restrict__ tokens,
                                                    const float* __restrict__ emb,
                                                    const float* __restrict__ W0,
                                                    const float* __restrict__ b0) {
    __shared__ __align__(16) float2 Ws2[20][128];
    __shared__ __align__(16) float  Es[20][68];
    __shared__ int toks[BATCH];

    const int t  = threadIdx.x;
    const int s  = blockIdx.y;
    const int k0 = blockIdx.x * 128;
    if (t < BATCH) toks[t] = tokens[t * SEQ + s];
    __syncthreads();

    const int tk = t & 15, tb = t >> 4;
    unsigned long long acc[8][2];
#pragma unroll
    for (int i = 0; i < 8; ++i) { acc[i][0] = 0ull; acc[i][1] = 0ull; }

    for (int it = 0; it < 15; ++it) {
        const int d0 = it * 20;
        for (int idx = t; idx < 20 * 128; idx += 256) {
            int r = idx >> 7, c = idx & 127;
            float v = W0[(size_t)(d0 + r) * G3 + k0 + c];
            Ws2[r][c] = make_float2(v, v);
        }
        for (int idx = t; idx < 20 * BATCH; idx += 256) {
            int b = idx / 20, d = idx % 20;
            Es[d][b] = emb[(size_t)toks[b] * HID + d0 + d];
        }
        __syncthreads();
#pragma unroll
        for (int d = 0; d < 20; ++d) {
            ulonglong2 es = *(const ulonglong2*)&Es[d][tb * 4];
            const ulonglong2* wp = (const ulonglong2*)&Ws2[d][tk * 8];
#pragma unroll
            for (int ii = 0; ii < 4; ++ii) {
                ulonglong2 w2 = wp[ii];
                acc[2*ii  ][0] = ffma2(w2.x, es.x, acc[2*ii  ][0]);
                acc[2*ii  ][1] = ffma2(w2.x, es.y, acc[2*ii  ][1]);
                acc[2*ii+1][0] = ffma2(w2.y, es.x, acc[2*ii+1][0]);
                acc[2*ii+1][1] = ffma2(w2.y, es.y, acc[2*ii+1][1]);
            }
        }
        __syncthreads();
    }
#pragma unroll
    for (int i = 0; i < 8; ++i) {
        const int k = k0 + tk * 8 + i;
        const float bias = b0[k];
        F2U a0, a1; a0.u = acc[i][0]; a1.u = acc[i][1];
        float* dst = &g_xg[((size_t)s * G3 + k) * BATCH + tb * 4];
        dst[0] = a0.f.x + bias;
        dst[1] = a0.f.y + bias;
        dst[2] = a1.f.x + bias;
        dst[3] = a1.f.y + bias;
    }
}

// ---------------- layer-1 input projection (FFMA2) ----------------
__global__ void __launch_bounds__(256) proj1_kernel(const float* __restrict__ W1,
                                                    const float* __restrict__ b1) {
    __shared__ __align__(16) float2 Ws2[32][128];
    __shared__ __align__(16) float  Es[32][68];

    const int t  = threadIdx.x;
    const int s  = blockIdx.y;
    const int k0 = blockIdx.x * 128;
    const int tk = t & 15, tb = t >> 4;

    unsigned long long acc[8][2];
#pragma unroll
    for (int i = 0; i < 8; ++i) { acc[i][0] = 0ull; acc[i][1] = 0ull; }

    for (int it = 0; it < 16; ++it) {
        const int u0 = it * 32;
        for (int idx = t; idx < 32 * 128; idx += 256) {
            int r = idx >> 7, c = idx & 127;
            float v = W1[(size_t)(u0 + r) * G3 + k0 + c];
            Ws2[r][c] = make_float2(v, v);
        }
        for (int idx = t; idx < 32 * BATCH; idx += 256) {
            int b = idx >> 5, u = idx & 31;
            Es[u][b] = g_y0[((size_t)s * BATCH + b) * UN + u0 + u];
        }
        __syncthreads();
#pragma unroll
        for (int d = 0; d < 32; ++d) {
            ulonglong2 es = *(const ulonglong2*)&Es[d][tb * 4];
            const ulonglong2* wp = (const ulonglong2*)&Ws2[d][tk * 8];
#pragma unroll
            for (int ii = 0; ii < 4; ++ii) {
                ulonglong2 w2 = wp[ii];
                acc[2*ii  ][0] = ffma2(w2.x, es.x, acc[2*ii  ][0]);
                acc[2*ii  ][1] = ffma2(w2.x, es.y, acc[2*ii  ][1]);
                acc[2*ii+1][0] = ffma2(w2.y, es.x, acc[2*ii+1][0]);
                acc[2*ii+1][1] = ffma2(w2.y, es.y, acc[2*ii+1][1]);
            }
        }
        __syncthreads();
    }
#pragma unroll
    for (int i = 0; i < 8; ++i) {
        const int k = k0 + tk * 8 + i;
        const float bias = b1[k];
        F2U a0, a1; a0.u = acc[i][0]; a1.u = acc[i][1];
        float* dst = &g_xg[((size_t)s * G3 + k) * BATCH + tb * 4];
        dst[0] = a0.f.x + bias;
        dst[1] = a0.f.y + bias;
        dst[2] = a1.f.x + bias;
        dst[3] = a1.f.y + bias;
    }
}

// ---------------- persistent GRU scan ----------------
// 128 CTAs x 512 threads. CTA = 8 unit-cols x 32 batch. U slice duplicated as
// f32x2 pairs in SMEM. 16 warps split K (32 each); FFMA2 inner loop; SMEM
// partial reduce; register-resident hprev; acquire/release grid barrier.
__global__ void __launch_bounds__(NTH, 1) gru_scan(const float* __restrict__ Umat,
                                                   const float* __restrict__ brec,
                                                   int layer1, float* __restrict__ out) {
    extern __shared__ float sm[];
    float2* u2    = (float2*)sm;          // 512*24 float2 = 24576 floats (96KB)
    float* part   = sm + 24576;           // [16][768] = 12288 floats (48KB)
    float* rg_s   = part + 12288;         // [768]
    float* bias_s = rg_s + 768;           // [768]

    const int t  = threadIdx.x;
    const int l  = t & 31;
    const int w  = t >> 5;
    const int c0 = (blockIdx.x >> 1) * 8;
    const int b0 = (blockIdx.x & 1) * 32;

    __shared__ unsigned s_base;
    if (t == 0) {
        unsigned gcur;
        asm volatile("ld.relaxed.gpu.global.u32 %0, [%1];" : "=r"(gcur) : "l"(&g_gen) : "memory");
        s_base = gcur;
    }

    // U slice, duplicated: u2[k*24 + g*8 + c] = (U[k][g*512+c0+c], same)
    for (int idx = t; idx < 512 * 24; idx += NTH) {
        int k = idx / 24, j = idx % 24;
        int g = j >> 3, c = j & 7;
        float v = Umat[(size_t)k * G3 + g * UN + c0 + c];
        u2[idx] = make_float2(v, v);
    }
    // recurrent bias mapped to output layout o = (g*8+c)*32+b
    for (int idx = t; idx < 768; idx += NTH) {
        int g = idx >> 8, c = (idx >> 5) & 7;
        bias_s[idx] = brec[g * UN + c0 + c];
    }
    // zero h buffer 0
    for (int idx = blockIdx.x * NTH + t; idx < UN * BATCH; idx += NCTA * NTH)
        __stcg(&(&g_h[0][0][0])[idx], 0.f);
    __syncthreads();
    const unsigned base = s_base;
    if (t == 0) grid_bar(1, base);
    __syncthreads();

    unsigned nbar = 1;
    int p = 0;
    float hprev = 0.f;
    const int gb_c  = t & 7;    // gate-thread col (t < 256)
    const int gb_bb = t >> 3;   // gate-thread batch

    for (int s = 0; s < SEQ; ++s) {
        // prefetch xg for gate threads (consumed after the dot loop)
        float xz = 0.f, xr = 0.f, xh = 0.f;
        if (t < 256) {
            const size_t bx = (size_t)s * G3 * BATCH;
            const int gc = c0 + gb_c, gbb = b0 + gb_bb;
            xz = __ldg(&g_xg[bx + (size_t)gc * BATCH + gbb]);
            xr = __ldg(&g_xg[bx + (size_t)(UN + gc) * BATCH + gbb]);
            xh = __ldg(&g_xg[bx + (size_t)(2 * UN + gc) * BATCH + gbb]);
        }

        const int kbase = w * KW;
        const int bp = l & 15, ch = l >> 4;
        unsigned long long acc[12];
#pragma unroll
        for (int i = 0; i < 12; ++i) acc[i] = 0ull;

        const unsigned long long* hrow = (const unsigned long long*)
            ((const float*)g_h + ((size_t)p * UN + kbase) * BATCH + b0 + 2 * bp);
        const float2* ubase = u2 + (size_t)kbase * 24 + ch * 4;
#pragma unroll 8
        for (int kk = 0; kk < KW; ++kk) {
            unsigned long long h2 = __ldcg(hrow + (size_t)kk * (BATCH / 2));
            const ulonglong2* up = (const ulonglong2*)(ubase + (size_t)kk * 24);
#pragma unroll
            for (int g = 0; g < 3; ++g) {
                ulonglong2 ua = up[g * 4];
                ulonglong2 ub = up[g * 4 + 1];
                acc[g*4+0] = ffma2(h2, ua.x, acc[g*4+0]);
                acc[g*4+1] = ffma2(h2, ua.y, acc[g*4+1]);
                acc[g*4+2] = ffma2(h2, ub.x, acc[g*4+2]);
                acc[g*4+3] = ffma2(h2, ub.y, acc[g*4+3]);
            }
        }
        // partials: part[w][(g*8 + ch*4 + ci)*32 + 2bp(+1)]
        {
            float* pw = part + w * 768 + ch * 128 + 2 * bp;
#pragma unroll
            for (int g = 0; g < 3; ++g)
#pragma unroll
                for (int ci = 0; ci < 4; ++ci)
                    *(unsigned long long*)&pw[g * 256 + ci * 32] = acc[g * 4 + ci];
        }
        __syncthreads();

        // reduce 16 partials + bias -> rg_s[768]
        {
            float v = bias_s[t];
#pragma unroll
            for (int ww = 0; ww < NW; ++ww) v += part[ww * 768 + t];
            rg_s[t] = v;
            if (t < 256) {
                float v2 = bias_s[512 + t];
#pragma unroll
                for (int ww = 0; ww < NW; ++ww) v2 += part[ww * 768 + 512 + t];
                rg_s[512 + t] = v2;
            }
        }
        __syncthreads();

        if (t < 256) {
            const int c = gb_c, bb = gb_bb;
            const int o = c * 32 + bb;
            const float rz = rg_s[o], rr = rg_s[256 + o], rh = rg_s[512 + o];
            const float z  = sigf(xz + rz);
            const float r  = sigf(xr + rr);
            const float hh = tanhfast(xh + r * rh);
            const float hn = z * hprev + (1.f - z) * hh;
            hprev = hn;
            const int gc = c0 + c, gbb = b0 + bb;
            __stcg(&g_h[p ^ 1][gc][gbb], hn);
            if (!layer1) {
                g_y0[((size_t)s * BATCH + gbb) * UN + gc] = hn;
            } else {
                out[((size_t)gbb * SEQ + s) * UN + gc] = hn;
                if (s == SEQ - 1)
                    out[(size_t)BATCH * SEQ * UN + (size_t)gbb * UN + gc] = hn;
            }
        }
        p ^= 1;
        if (s != SEQ - 1) {
            __syncthreads();
            if (t == 0) grid_bar(++nbar, base);
            __syncthreads();
        }
    }
}

// ---------------- launch ----------------
extern "C" void kernel_launch(void* const* d_in, const int* in_sizes, int n_in,
                              void* d_out, int out_size) {
    const int*   tokens = (const int*)d_in[0];
    const float* emb    = (const float*)d_in[1];
    const float* W0     = (const float*)d_in[2];
    const float* U0     = (const float*)d_in[3];
    const float* b0     = (const float*)d_in[4];
    const float* W1     = (const float*)d_in[5];
    const float* U1     = (const float*)d_in[6];
    const float* b1     = (const float*)d_in[7];
    float* out = (float*)d_out;

    // u2 (24576 floats) + part (12288) + rg_s (768) + bias_s (768) = 38400 floats = 150 KB
    const size_t shmem = (24576 + 12288 + 768 + 768) * sizeof(float);
    cudaFuncSetAttribute(gru_scan, cudaFuncAttributeMaxDynamicSharedMemorySize, (int)shmem);

    dim3 pgrid(12, 512);
    proj0_kernel<<<pgrid, 256>>>(tokens, emb, W0, b0);
    gru_scan<<<NCTA, NTH, shmem>>>(U0, b0 + G3, 0, nullptr);
    proj1_kernel<<<pgrid, 256>>>(W1, b1);
    gru_scan<<<NCTA, NTH, shmem>>>(U1, b1 + G3, 1, out);
}